// round 11
// baseline (speedup 1.0000x reference)
#include <cuda_runtime.h>
#include <cuda_fp16.h>
#include <math.h>
#include <stdint.h>
#include <string.h>

#define NNODES 100000
#define NEDGES 1600000
#define NB_SCAN 98   /* ceil(NNODES/1024) */

// ------------------------- device scratch (no allocs allowed) ---------------
__device__ int   g_cnt[NNODES];          // counts; self-zeroed by k_fill4
__device__ int   g_rowptr[NNODES + 1];
__device__ int   g_col[NEDGES];
__device__ float g_dinv[NNODES];
__device__ int   g_bsums[NB_SCAN];
__device__ __align__(16) __half g_hA[(size_t)NNODES * 64];
__device__ __align__(16) __half g_hB[(size_t)NNODES * 64];
// doubles as: INTERLEAVED fp16 copy of x (launches 2-4), then y2 natural (9+)
__device__ __align__(16) __half g_h128[(size_t)NNODES * 128];
// fp16 weights, K-major [n][k], k interleaved in 16-groups for mma frags
__device__ __align__(16) __half g_Whi[24576];

// ----------------------------- helpers --------------------------------------
__device__ __forceinline__ uint32_t h2u(__half2 h) {
    uint32_t u; memcpy(&u, &h, 4); return u;
}
__device__ __forceinline__ void mma_f16(float c[4],
    uint32_t a0, uint32_t a1, uint32_t a2, uint32_t a3,
    uint32_t b0, uint32_t b1)
{
    asm volatile("mma.sync.aligned.m16n8k16.row.col.f32.f16.f16.f32 "
        "{%0,%1,%2,%3}, {%4,%5,%6,%7}, {%8,%9}, {%0,%1,%2,%3};"
        : "+f"(c[0]), "+f"(c[1]), "+f"(c[2]), "+f"(c[3])
        : "r"(a0), "r"(a1), "r"(a2), "r"(a3), "r"(b0), "r"(b1));
}

// ---------------- CSR count + x->fp16 interleaved convert (fused) -----------
__global__ void k_count_conv(const int* __restrict__ dst,
                             const float* __restrict__ x,
                             uint4* __restrict__ hX4) {
    int t = blockIdx.x * blockDim.x + threadIdx.x;
    if (t >= NEDGES) return;
    atomicAdd(&g_cnt[dst[t]], 1);
    // conversion: exactly NNODES*16 = NEDGES uint4 units, interleave applied
    int row = t >> 4, j = t & 15;
    int g16 = (j >> 1) * 16, h4 = (j & 1) * 4;
    const float* p = &x[(size_t)row * 128 + g16 + h4];
    float4 f0 = *(const float4*)p;
    float4 f1 = *(const float4*)(p + 8);
    uint4 o;
    o.x = h2u(__floats2half2_rn(f0.x, f0.y));
    o.y = h2u(__floats2half2_rn(f1.x, f1.y));
    o.z = h2u(__floats2half2_rn(f0.z, f0.w));
    o.w = h2u(__floats2half2_rn(f1.z, f1.w));
    hX4[t] = o;
}

__global__ void k_bsum() {
    __shared__ int s[256];
    int t = threadIdx.x;
    int base = blockIdx.x * 1024 + t * 4;
    int sum = 0;
#pragma unroll
    for (int i = 0; i < 4; i++) { int idx = base + i; if (idx < NNODES) sum += g_cnt[idx]; }
    s[t] = sum; __syncthreads();
    for (int off = 128; off > 0; off >>= 1) {
        if (t < off) s[t] += s[t + off];
        __syncthreads();
    }
    if (t == 0) g_bsums[blockIdx.x] = s[0];
}

__global__ void k_writeptr() {
    __shared__ int s[256];
    __shared__ int sb[NB_SCAN];
    __shared__ int s_off;
    int t = threadIdx.x;
    if (t < NB_SCAN) sb[t] = g_bsums[t];

    int base = blockIdx.x * 1024 + t * 4;
    int c[4]; int sum = 0;
#pragma unroll
    for (int i = 0; i < 4; i++) {
        int idx = base + i;
        c[i] = (idx < NNODES) ? g_cnt[idx] : 0;
        sum += c[i];
    }
    s[t] = sum; __syncthreads();
    if (t == 0) {
        int r = 0;
        for (int i = 0; i < (int)blockIdx.x; i++) r += sb[i];
        s_off = r;
    }
    for (int off = 1; off < 256; off <<= 1) {
        int v = (t >= off) ? s[t - off] : 0;
        __syncthreads();
        s[t] += v;
        __syncthreads();
    }
    int excl = s[t] - sum + s_off;
#pragma unroll
    for (int i = 0; i < 4; i++) {
        int idx = base + i;
        if (idx < NNODES) {
            g_rowptr[idx] = excl;
            g_dinv[idx] = rsqrtf((float)c[i] + 1.0f);
            excl += c[i];
        }
    }
    if (blockIdx.x == 0 && t == 0) g_rowptr[NNODES] = NEDGES;
}

__global__ void k_fill4(const int4* __restrict__ src4, const int4* __restrict__ dst4) {
    int e = blockIdx.x * blockDim.x + threadIdx.x;
    if (e >= NEDGES / 4) return;
    int4 d = dst4[e], s = src4[e];
    int p0 = atomicSub(&g_cnt[d.x], 1) - 1;
    int p1 = atomicSub(&g_cnt[d.y], 1) - 1;
    int p2 = atomicSub(&g_cnt[d.z], 1) - 1;
    int p3 = atomicSub(&g_cnt[d.w], 1) - 1;
    g_col[g_rowptr[d.x] + p0] = s.x;
    g_col[g_rowptr[d.y] + p1] = s.y;
    g_col[g_rowptr[d.z] + p2] = s.z;
    g_col[g_rowptr[d.w] + p3] = s.w;
}

// -------- weight prep: fp32 -> fp16, K-major, 16-group interleaved ----------
__global__ void k_wsplit(const float* __restrict__ W1, const float* __restrict__ W2,
                         const float* __restrict__ W3) {
    int i = blockIdx.x * 256 + threadIdx.x;
    if (i >= 24576) return;
    const float* W; int IN, OUT, idx;
    if (i < 8192)       { W = W1; IN = 128; OUT = 64;  idx = i; }
    else if (i < 16384) { W = W2; IN = 64;  OUT = 128; idx = i - 8192; }
    else                { W = W3; IN = 128; OUT = 64;  idx = i - 16384; }
    int n = idx / IN, s = idx % IN;
    int g16 = s & ~15, u = s & 15;
    int k = g16 + ((u >> 2) & 3) * 2 + ((u >> 1) & 1) * 8 + (u & 1);
    g_Whi[i] = __float2half_rn(W[k * OUT + n]);
}

// --------------------------- FP16 mma GEMM ----------------------------------
// C[:, bn0:bn0+64] = A[N x IN] @ W-tile (fp16, single MMA term).
// CTA: 128 rows x 64 cols, 256 thr = 8 warps; warp = 16 rows = one m16 slab.
// (More warps/SM for latency hiding; smem unchanged -> 4 CTAs/SM = 32 warps.)
// Smem rows = IN+16 halves (stride == 32 mod 128 bytes -> conflict-free LDS.64).
// AINT: A already interleaved in global (pure uint4 copy staging);
// else natural fp16, staging applies the 16-group interleave shuffle.
template <int IN, int OUTTOT, bool AINT, bool SCALE, bool BIAS, bool RELU>
__global__ __launch_bounds__(256, 4) void k_mma(
    const __half* __restrict__ A,
    const __half* __restrict__ Whi,
    const float* __restrict__ bias, __half* __restrict__ C)
{
    extern __shared__ __half sh[];
    constexpr int RSH = IN + 16;
    constexpr int NK16 = IN / 16;
    __half* sA  = sh;                       // 128 x RSH
    __half* sBh = sh + 128 * RSH;           // 64 x RSH

    int t = threadIdx.x;
    int row0 = blockIdx.x * 128;
    int bn0  = blockIdx.y * 64;

    // --- stage A ---
    if (AINT) {
#pragma unroll
        for (int i = 0; i < IN / 16; i++) {          // 128*(IN/8)/256 uint4
            int idx = t + i * 256;
            int row = idx / (IN / 8);
            int c8  = (idx % (IN / 8)) * 8;
            uint4 v = make_uint4(0, 0, 0, 0);
            if (row0 + row < NNODES)
                v = *(const uint4*)&A[(size_t)(row0 + row) * IN + c8];
            *(uint4*)((uint32_t*)sA + (row * RSH + c8) / 2) = v;
        }
    } else {
#pragma unroll
        for (int i = 0; i < IN / 32; i++) {          // 128*(IN/16)/256 units
            int idx = t + i * 256;
            int row = idx / (IN / 16);
            int g16 = (idx % (IN / 16)) * 16;
            uint4 v0 = make_uint4(0, 0, 0, 0), v1 = v0;
            if (row0 + row < NNODES) {
                const uint4* p = (const uint4*)&A[(size_t)(row0 + row) * IN + g16];
                v0 = p[0]; v1 = p[1];
            }
            uint4* dw = (uint4*)((uint32_t*)sA + (row * RSH + g16) / 2);
            dw[0] = make_uint4(v0.x, v1.x, v0.y, v1.y);
            dw[1] = make_uint4(v0.z, v1.z, v0.w, v1.w);
        }
    }
    // --- stage B ---
#pragma unroll
    for (int i = 0; i < IN / 32; i++) {              // 64*(IN/8)/256 uint4
        int idx = t + i * 256;
        int n  = idx / (IN / 8);
        int c8 = (idx % (IN / 8)) * 8;
        *(uint4*)((uint32_t*)sBh + (n * RSH + c8) / 2) =
            *(const uint4*)&Whi[(size_t)(bn0 + n) * IN + c8];
    }
    __syncthreads();

    int lane = t & 31, warp = t >> 5;
    int g = lane >> 2, j = lane & 3;
    int wb = warp * 16;                              // one m16 slab per warp

    float c0[8][4];
#pragma unroll
    for (int n = 0; n < 8; n++)
        c0[n][0] = c0[n][1] = c0[n][2] = c0[n][3] = 0.f;

    const uint32_t* sAw  = (const uint32_t*)sA;
    const uint32_t* sBhw = (const uint32_t*)sBh;
    int a0w = (wb + g) * (RSH / 2) + j * 2;
    int a1w = a0w + 8 * (RSH / 2);
    int bw  = g * (RSH / 2) + j * 2;

#pragma unroll
    for (int kk = 0; kk < NK16; kk++) {
        int ko = kk * 8;
        uint2 r0 = *(const uint2*)&sAw[a0w + ko];    // rows wb+g
        uint2 r1 = *(const uint2*)&sAw[a1w + ko];    // rows wb+g+8
#pragma unroll
        for (int n = 0; n < 8; n++) {
            uint2 bh = *(const uint2*)&sBhw[bw + n * 8 * (RSH / 2) + ko];
            mma_f16(c0[n], r0.x, r1.x, r0.y, r1.y, bh.x, bh.y);
        }
    }

    // --- epilogue: bias/relu/dinv, pack fp16, STG.32 (natural layout) ---
    {
        int r0 = row0 + wb + g, r1 = r0 + 8;
        float d0 = 1.f, d1 = 1.f;
        if (SCALE) {
            if (r0 < NNODES) d0 = g_dinv[r0];
            if (r1 < NNODES) d1 = g_dinv[r1];
        }
#pragma unroll
        for (int n = 0; n < 8; n++) {
            int col = bn0 + n * 8 + 2 * j;
            float b0 = 0.f, b1 = 0.f;
            if (BIAS) { b0 = __ldg(&bias[col]); b1 = __ldg(&bias[col + 1]); }
            float v0 = c0[n][0] + b0, v1 = c0[n][1] + b1;
            float v2 = c0[n][2] + b0, v3 = c0[n][3] + b1;
            if (RELU) {
                v0 = fmaxf(v0, 0.f); v1 = fmaxf(v1, 0.f);
                v2 = fmaxf(v2, 0.f); v3 = fmaxf(v3, 0.f);
            }
            if (SCALE) { v0 *= d0; v1 *= d0; v2 *= d1; v3 *= d1; }
            if (r0 < NNODES)
                *(uint32_t*)&C[(size_t)r0 * OUTTOT + col] =
                    h2u(__floats2half2_rn(v0, v1));
            if (r1 < NNODES)
                *(uint32_t*)&C[(size_t)r1 * OUTTOT + col] =
                    h2u(__floats2half2_rn(v2, v3));
        }
    }
}

// ----------------------------- Aggregation (fp16 gather) --------------------
template <bool EDGESCALE, bool BIAS, bool RELU, bool POSTSCALE, bool OUT32>
__global__ __launch_bounds__(256) void k_agg64(
    const __half2* __restrict__ U, const float* __restrict__ bias,
    void* __restrict__ OutV)
{
    int warp = (blockIdx.x * blockDim.x + threadIdx.x) >> 5;
    int lane = threadIdx.x & 31;
    if (warp >= NNODES) return;
    int d = warp;

    float di = g_dinv[d];
    float selfs = EDGESCALE ? di : 1.0f;
    float2 u = __half22float2(U[(size_t)d * 32 + lane]);
    float2 acc  = make_float2(u.x * selfs, u.y * selfs);
    float2 acc2 = make_float2(0.f, 0.f);

    int b = g_rowptr[d], e = g_rowptr[d + 1];
    int j = b;
    for (; j + 1 < e; j += 2) {
        int s0 = __ldg(&g_col[j]);
        int s1 = __ldg(&g_col[j + 1]);
        float2 v0 = __half22float2(__ldg(&U[(size_t)s0 * 32 + lane]));
        float2 v1 = __half22float2(__ldg(&U[(size_t)s1 * 32 + lane]));
        float w0 = EDGESCALE ? __ldg(&g_dinv[s0]) : 1.0f;
        float w1 = EDGESCALE ? __ldg(&g_dinv[s1]) : 1.0f;
        acc.x  = fmaf(v0.x, w0, acc.x);  acc.y  = fmaf(v0.y, w0, acc.y);
        acc2.x = fmaf(v1.x, w1, acc2.x); acc2.y = fmaf(v1.y, w1, acc2.y);
    }
    if (j < e) {
        int s0 = __ldg(&g_col[j]);
        float2 v0 = __half22float2(__ldg(&U[(size_t)s0 * 32 + lane]));
        float w0 = EDGESCALE ? __ldg(&g_dinv[s0]) : 1.0f;
        acc.x = fmaf(v0.x, w0, acc.x); acc.y = fmaf(v0.y, w0, acc.y);
    }
    acc.x += acc2.x; acc.y += acc2.y;

    float ox = acc.x * di, oy = acc.y * di;
    if (BIAS) {
        float2 bb = *(const float2*)&bias[2 * lane];
        ox += bb.x; oy += bb.y;
    }
    if (RELU) { ox = fmaxf(ox, 0.f); oy = fmaxf(oy, 0.f); }
    if (POSTSCALE) { ox *= di; oy *= di; }
    if (OUT32) {
        *(float2*)&((float*)OutV)[(size_t)d * 64 + 2 * lane] = make_float2(ox, oy);
    } else {
        ((__half2*)OutV)[(size_t)d * 32 + lane] = __floats2half2_rn(ox, oy);
    }
}

// ------------------------------- launch --------------------------------------
extern "C" void kernel_launch(void* const* d_in, const int* in_sizes, int n_in,
                              void* d_out, int out_size)
{
    const float* x  = (const float*)d_in[0];
    const int*   ei = (const int*)d_in[1];
    const float* W1 = (const float*)d_in[2];
    const float* b1 = (const float*)d_in[3];
    const float* W2 = (const float*)d_in[4];
    const float* b2 = (const float*)d_in[5];
    const float* W3 = (const float*)d_in[6];
    const float* b3 = (const float*)d_in[7];
    float* out = (float*)d_out;

    const int* src = ei;
    const int* dst = ei + NEDGES;

    __half *hA, *hB, *h128, *whi;
    cudaGetSymbolAddress((void**)&hA,   g_hA);
    cudaGetSymbolAddress((void**)&hB,   g_hB);
    cudaGetSymbolAddress((void**)&h128, g_h128);
    cudaGetSymbolAddress((void**)&whi,  g_Whi);

    const int EB = (NEDGES + 255) / 256;
    const int GB = (NNODES + 127) / 128;
    const int AB = (NNODES * 32 + 255) / 256;

    const int SM1 = 192 * 144 * 2;   // 55296 -> 4 CTAs/SM (32 warps)
    const int SM2 = 192 * 80 * 2;    // 30720
    cudaFuncSetAttribute((const void*)k_mma<128, 64, true, false, false, false>,
                         cudaFuncAttributeMaxDynamicSharedMemorySize, SM1);
    cudaFuncSetAttribute((const void*)k_mma<64, 128, false, false, true, true>,
                         cudaFuncAttributeMaxDynamicSharedMemorySize, SM2);
    cudaFuncSetAttribute((const void*)k_mma<128, 64, false, true, false, false>,
                         cudaFuncAttributeMaxDynamicSharedMemorySize, SM1);

    // --- prep + CSR; GEMM1 kept in profiled slot #4 ---
    k_wsplit<<<96, 256>>>(W1, W2, W3);                                   // 1
    k_count_conv<<<EB, 256>>>(dst, x, (uint4*)h128);                     // 2
    k_bsum<<<NB_SCAN, 256>>>();                                          // 3
    k_mma<128, 64, true, false, false, false><<<dim3(GB, 1), 256, SM1>>>(
        h128, whi, nullptr, hA);                                         // 4
    k_writeptr<<<NB_SCAN, 256>>>();                                      // 5
    k_fill4<<<(NEDGES / 4 + 255) / 256, 256>>>(
        (const int4*)src, (const int4*)dst);                             // 6

    // --- Layer 1 agg ---
    k_agg64<true, true, true, true, false><<<AB, 256>>>(
        (const __half2*)hA, b1, hB);                                     // 7

    // --- Layer 2 ---
    k_agg64<false, false, false, false, false><<<AB, 256>>>(
        (const __half2*)hB, nullptr, hA);                                // 8
    k_mma<64, 128, false, false, true, true><<<dim3(GB, 2), 256, SM2>>>(
        hA, whi + 8192, b2, h128);                                       // 9

    // --- Layer 3 ---
    k_mma<128, 64, false, true, false, false><<<dim3(GB, 1), 256, SM1>>>(
        h128, whi + 16384, nullptr, hB);                                 // 10
    k_agg64<false, true, false, false, true><<<AB, 256>>>(
        (const __half2*)hB, b3, out);                                    // 11

    (void)in_sizes; (void)n_in; (void)out_size;
}

// round 12
// speedup vs baseline: 1.0329x; 1.0329x over previous
#include <cuda_runtime.h>
#include <cuda_fp16.h>
#include <math.h>
#include <stdint.h>
#include <string.h>

#define NNODES 100000
#define NEDGES 1600000
#define NB_SCAN 98   /* ceil(NNODES/1024) */

// ------------------------- device scratch (no allocs allowed) ---------------
__device__ int   g_cnt[NNODES];          // counts; self-zeroed by k_fill4
__device__ int   g_rowptr[NNODES + 1];
__device__ int   g_col[NEDGES];
__device__ float g_dinv[NNODES];
__device__ int   g_bsums[NB_SCAN];
__device__ __align__(16) __half g_hA[(size_t)NNODES * 64];
__device__ __align__(16) __half g_hB[(size_t)NNODES * 64];
// doubles as: INTERLEAVED fp16 copy of x (early), then y2 natural (late)
__device__ __align__(16) __half g_h128[(size_t)NNODES * 128];
// fp16 weights, K-major [n][k], k interleaved in 16-groups for mma frags
__device__ __align__(16) __half g_Whi[24576];

// ----------------------------- helpers --------------------------------------
__device__ __forceinline__ uint32_t h2u(__half2 h) {
    uint32_t u; memcpy(&u, &h, 4); return u;
}
__device__ __forceinline__ void mma_f16(float c[4],
    uint32_t a0, uint32_t a1, uint32_t a2, uint32_t a3,
    uint32_t b0, uint32_t b1)
{
    asm volatile("mma.sync.aligned.m16n8k16.row.col.f32.f16.f16.f32 "
        "{%0,%1,%2,%3}, {%4,%5,%6,%7}, {%8,%9}, {%0,%1,%2,%3};"
        : "+f"(c[0]), "+f"(c[1]), "+f"(c[2]), "+f"(c[3])
        : "r"(a0), "r"(a1), "r"(a2), "r"(a3), "r"(b0), "r"(b1));
}

// ------ fused prep: edge count + x->fp16 interleave + weight fp16 prep ------
// Thread t: one count atomic + one uint4 of converted x; threads < 24576 also
// convert one weight element (K-major, 16-group mma interleave).
__global__ void k_prep(const int* __restrict__ dst,
                       const float* __restrict__ x,
                       uint4* __restrict__ hX4,
                       const float* __restrict__ W1,
                       const float* __restrict__ W2,
                       const float* __restrict__ W3) {
    int t = blockIdx.x * blockDim.x + threadIdx.x;
    if (t < 24576) {
        const float* W; int IN, OUT, idx;
        if (t < 8192)       { W = W1; IN = 128; OUT = 64;  idx = t; }
        else if (t < 16384) { W = W2; IN = 64;  OUT = 128; idx = t - 8192; }
        else                { W = W3; IN = 128; OUT = 64;  idx = t - 16384; }
        int n = idx / IN, s = idx % IN;
        int g16 = s & ~15, u = s & 15;
        int k = g16 + ((u >> 2) & 3) * 2 + ((u >> 1) & 1) * 8 + (u & 1);
        g_Whi[t] = __float2half_rn(W[k * OUT + n]);
    }
    if (t >= NEDGES) return;
    atomicAdd(&g_cnt[dst[t]], 1);
    // conversion: exactly NNODES*16 = NEDGES uint4 units, interleave applied
    int row = t >> 4, j = t & 15;
    int g16 = (j >> 1) * 16, h4 = (j & 1) * 4;
    const float* p = &x[(size_t)row * 128 + g16 + h4];
    float4 f0 = *(const float4*)p;
    float4 f1 = *(const float4*)(p + 8);
    uint4 o;
    o.x = h2u(__floats2half2_rn(f0.x, f0.y));
    o.y = h2u(__floats2half2_rn(f1.x, f1.y));
    o.z = h2u(__floats2half2_rn(f0.z, f0.w));
    o.w = h2u(__floats2half2_rn(f1.z, f1.w));
    hX4[t] = o;
}

__global__ void k_bsum() {
    __shared__ int s[256];
    int t = threadIdx.x;
    int base = blockIdx.x * 1024 + t * 4;
    int sum = 0;
#pragma unroll
    for (int i = 0; i < 4; i++) { int idx = base + i; if (idx < NNODES) sum += g_cnt[idx]; }
    s[t] = sum; __syncthreads();
    for (int off = 128; off > 0; off >>= 1) {
        if (t < off) s[t] += s[t + off];
        __syncthreads();
    }
    if (t == 0) g_bsums[blockIdx.x] = s[0];
}

__global__ void k_writeptr() {
    __shared__ int s[256];
    __shared__ int sb[NB_SCAN];
    __shared__ int s_off;
    int t = threadIdx.x;
    if (t < NB_SCAN) sb[t] = g_bsums[t];

    int base = blockIdx.x * 1024 + t * 4;
    int c[4]; int sum = 0;
#pragma unroll
    for (int i = 0; i < 4; i++) {
        int idx = base + i;
        c[i] = (idx < NNODES) ? g_cnt[idx] : 0;
        sum += c[i];
    }
    s[t] = sum; __syncthreads();
    if (t == 0) {
        int r = 0;
        for (int i = 0; i < (int)blockIdx.x; i++) r += sb[i];
        s_off = r;
    }
    for (int off = 1; off < 256; off <<= 1) {
        int v = (t >= off) ? s[t - off] : 0;
        __syncthreads();
        s[t] += v;
        __syncthreads();
    }
    int excl = s[t] - sum + s_off;
#pragma unroll
    for (int i = 0; i < 4; i++) {
        int idx = base + i;
        if (idx < NNODES) {
            g_rowptr[idx] = excl;
            g_dinv[idx] = rsqrtf((float)c[i] + 1.0f);
            excl += c[i];
        }
    }
    if (blockIdx.x == 0 && t == 0) g_rowptr[NNODES] = NEDGES;
}

__global__ void k_fill4(const int4* __restrict__ src4, const int4* __restrict__ dst4) {
    int e = blockIdx.x * blockDim.x + threadIdx.x;
    if (e >= NEDGES / 4) return;
    int4 d = dst4[e], s = src4[e];
    int p0 = atomicSub(&g_cnt[d.x], 1) - 1;
    int p1 = atomicSub(&g_cnt[d.y], 1) - 1;
    int p2 = atomicSub(&g_cnt[d.z], 1) - 1;
    int p3 = atomicSub(&g_cnt[d.w], 1) - 1;
    g_col[g_rowptr[d.x] + p0] = s.x;
    g_col[g_rowptr[d.y] + p1] = s.y;
    g_col[g_rowptr[d.z] + p2] = s.z;
    g_col[g_rowptr[d.w] + p3] = s.w;
}

// --------------------------- FP16 mma GEMM ----------------------------------
// C[:, bn0:bn0+64] = A[N x IN] @ W-tile (fp16, single MMA term).
// CTA: 128 rows x 64 cols, 256 thr = 8 warps; warp = 16 rows = one m16 slab.
// Smem rows = IN+16 halves (stride == 32 mod 128 bytes -> conflict-free LDS.64).
// AINT: A already interleaved in global (pure uint4 copy staging);
// else natural fp16, staging applies the 16-group interleave shuffle.
template <int IN, int OUTTOT, bool AINT, bool SCALE, bool BIAS, bool RELU>
__global__ __launch_bounds__(256, 4) void k_mma(
    const __half* __restrict__ A,
    const __half* __restrict__ Whi,
    const float* __restrict__ bias, __half* __restrict__ C)
{
    extern __shared__ __half sh[];
    constexpr int RSH = IN + 16;
    constexpr int NK16 = IN / 16;
    __half* sA  = sh;                       // 128 x RSH
    __half* sBh = sh + 128 * RSH;           // 64 x RSH

    int t = threadIdx.x;
    int row0 = blockIdx.x * 128;
    int bn0  = blockIdx.y * 64;

    // --- stage A ---
    if (AINT) {
#pragma unroll
        for (int i = 0; i < IN / 16; i++) {
            int idx = t + i * 256;
            int row = idx / (IN / 8);
            int c8  = (idx % (IN / 8)) * 8;
            uint4 v = make_uint4(0, 0, 0, 0);
            if (row0 + row < NNODES)
                v = *(const uint4*)&A[(size_t)(row0 + row) * IN + c8];
            *(uint4*)((uint32_t*)sA + (row * RSH + c8) / 2) = v;
        }
    } else {
#pragma unroll
        for (int i = 0; i < IN / 32; i++) {
            int idx = t + i * 256;
            int row = idx / (IN / 16);
            int g16 = (idx % (IN / 16)) * 16;
            uint4 v0 = make_uint4(0, 0, 0, 0), v1 = v0;
            if (row0 + row < NNODES) {
                const uint4* p = (const uint4*)&A[(size_t)(row0 + row) * IN + g16];
                v0 = p[0]; v1 = p[1];
            }
            uint4* dw = (uint4*)((uint32_t*)sA + (row * RSH + g16) / 2);
            dw[0] = make_uint4(v0.x, v1.x, v0.y, v1.y);
            dw[1] = make_uint4(v0.z, v1.z, v0.w, v1.w);
        }
    }
    // --- stage B ---
#pragma unroll
    for (int i = 0; i < IN / 32; i++) {
        int idx = t + i * 256;
        int n  = idx / (IN / 8);
        int c8 = (idx % (IN / 8)) * 8;
        *(uint4*)((uint32_t*)sBh + (n * RSH + c8) / 2) =
            *(const uint4*)&Whi[(size_t)(bn0 + n) * IN + c8];
    }
    __syncthreads();

    int lane = t & 31, warp = t >> 5;
    int g = lane >> 2, j = lane & 3;
    int wb = warp * 16;

    float c0[8][4];
#pragma unroll
    for (int n = 0; n < 8; n++)
        c0[n][0] = c0[n][1] = c0[n][2] = c0[n][3] = 0.f;

    const uint32_t* sAw  = (const uint32_t*)sA;
    const uint32_t* sBhw = (const uint32_t*)sBh;
    int a0w = (wb + g) * (RSH / 2) + j * 2;
    int a1w = a0w + 8 * (RSH / 2);
    int bw  = g * (RSH / 2) + j * 2;

#pragma unroll
    for (int kk = 0; kk < NK16; kk++) {
        int ko = kk * 8;
        uint2 r0 = *(const uint2*)&sAw[a0w + ko];
        uint2 r1 = *(const uint2*)&sAw[a1w + ko];
#pragma unroll
        for (int n = 0; n < 8; n++) {
            uint2 bh = *(const uint2*)&sBhw[bw + n * 8 * (RSH / 2) + ko];
            mma_f16(c0[n], r0.x, r1.x, r0.y, r1.y, bh.x, bh.y);
        }
    }

    // --- epilogue: bias/relu/dinv, pack fp16, STG.32 (natural layout) ---
    {
        int r0 = row0 + wb + g, r1 = r0 + 8;
        float d0 = 1.f, d1 = 1.f;
        if (SCALE) {
            if (r0 < NNODES) d0 = g_dinv[r0];
            if (r1 < NNODES) d1 = g_dinv[r1];
        }
#pragma unroll
        for (int n = 0; n < 8; n++) {
            int col = bn0 + n * 8 + 2 * j;
            float b0 = 0.f, b1 = 0.f;
            if (BIAS) { b0 = __ldg(&bias[col]); b1 = __ldg(&bias[col + 1]); }
            float v0 = c0[n][0] + b0, v1 = c0[n][1] + b1;
            float v2 = c0[n][2] + b0, v3 = c0[n][3] + b1;
            if (RELU) {
                v0 = fmaxf(v0, 0.f); v1 = fmaxf(v1, 0.f);
                v2 = fmaxf(v2, 0.f); v3 = fmaxf(v3, 0.f);
            }
            if (SCALE) { v0 *= d0; v1 *= d0; v2 *= d1; v3 *= d1; }
            if (r0 < NNODES)
                *(uint32_t*)&C[(size_t)r0 * OUTTOT + col] =
                    h2u(__floats2half2_rn(v0, v1));
            if (r1 < NNODES)
                *(uint32_t*)&C[(size_t)r1 * OUTTOT + col] =
                    h2u(__floats2half2_rn(v2, v3));
        }
    }
}

// ----------------------------- Aggregation (fp16 gather) --------------------
template <bool EDGESCALE, bool BIAS, bool RELU, bool POSTSCALE, bool OUT32>
__global__ __launch_bounds__(256) void k_agg64(
    const __half2* __restrict__ U, const float* __restrict__ bias,
    void* __restrict__ OutV)
{
    int warp = (blockIdx.x * blockDim.x + threadIdx.x) >> 5;
    int lane = threadIdx.x & 31;
    if (warp >= NNODES) return;
    int d = warp;

    float di = g_dinv[d];
    float selfs = EDGESCALE ? di : 1.0f;
    float2 u = __half22float2(U[(size_t)d * 32 + lane]);
    float2 acc  = make_float2(u.x * selfs, u.y * selfs);
    float2 acc2 = make_float2(0.f, 0.f);

    int b = g_rowptr[d], e = g_rowptr[d + 1];
    int j = b;
    for (; j + 1 < e; j += 2) {
        int s0 = __ldg(&g_col[j]);
        int s1 = __ldg(&g_col[j + 1]);
        float2 v0 = __half22float2(__ldg(&U[(size_t)s0 * 32 + lane]));
        float2 v1 = __half22float2(__ldg(&U[(size_t)s1 * 32 + lane]));
        float w0 = EDGESCALE ? __ldg(&g_dinv[s0]) : 1.0f;
        float w1 = EDGESCALE ? __ldg(&g_dinv[s1]) : 1.0f;
        acc.x  = fmaf(v0.x, w0, acc.x);  acc.y  = fmaf(v0.y, w0, acc.y);
        acc2.x = fmaf(v1.x, w1, acc2.x); acc2.y = fmaf(v1.y, w1, acc2.y);
    }
    if (j < e) {
        int s0 = __ldg(&g_col[j]);
        float2 v0 = __half22float2(__ldg(&U[(size_t)s0 * 32 + lane]));
        float w0 = EDGESCALE ? __ldg(&g_dinv[s0]) : 1.0f;
        acc.x = fmaf(v0.x, w0, acc.x); acc.y = fmaf(v0.y, w0, acc.y);
    }
    acc.x += acc2.x; acc.y += acc2.y;

    float ox = acc.x * di, oy = acc.y * di;
    if (BIAS) {
        float2 bb = *(const float2*)&bias[2 * lane];
        ox += bb.x; oy += bb.y;
    }
    if (RELU) { ox = fmaxf(ox, 0.f); oy = fmaxf(oy, 0.f); }
    if (POSTSCALE) { ox *= di; oy *= di; }
    if (OUT32) {
        *(float2*)&((float*)OutV)[(size_t)d * 64 + 2 * lane] = make_float2(ox, oy);
    } else {
        ((__half2*)OutV)[(size_t)d * 32 + lane] = __floats2half2_rn(ox, oy);
    }
}

// ------------------------------- launch --------------------------------------
extern "C" void kernel_launch(void* const* d_in, const int* in_sizes, int n_in,
                              void* d_out, int out_size)
{
    const float* x  = (const float*)d_in[0];
    const int*   ei = (const int*)d_in[1];
    const float* W1 = (const float*)d_in[2];
    const float* b1 = (const float*)d_in[3];
    const float* W2 = (const float*)d_in[4];
    const float* b2 = (const float*)d_in[5];
    const float* W3 = (const float*)d_in[6];
    const float* b3 = (const float*)d_in[7];
    float* out = (float*)d_out;

    const int* src = ei;
    const int* dst = ei + NEDGES;

    __half *hA, *hB, *h128, *whi;
    cudaGetSymbolAddress((void**)&hA,   g_hA);
    cudaGetSymbolAddress((void**)&hB,   g_hB);
    cudaGetSymbolAddress((void**)&h128, g_h128);
    cudaGetSymbolAddress((void**)&whi,  g_Whi);

    const int EB = (NEDGES + 255) / 256;
    const int GB = (NNODES + 127) / 128;
    const int AB = (NNODES * 32 + 255) / 256;

    const int SM1 = 192 * 144 * 2;   // 55296 -> 4 CTAs/SM
    const int SM2 = 192 * 80 * 2;    // 30720
    cudaFuncSetAttribute((const void*)k_mma<128, 64, true, false, false, false>,
                         cudaFuncAttributeMaxDynamicSharedMemorySize, SM1);
    cudaFuncSetAttribute((const void*)k_mma<64, 128, false, false, true, true>,
                         cudaFuncAttributeMaxDynamicSharedMemorySize, SM2);
    cudaFuncSetAttribute((const void*)k_mma<128, 64, false, true, false, false>,
                         cudaFuncAttributeMaxDynamicSharedMemorySize, SM1);

    // side stream + events for the parallel CSR branch (fork/join in capture)
    cudaStream_t s1;
    cudaStreamCreateWithFlags(&s1, cudaStreamNonBlocking);
    cudaEvent_t e1, e2;
    cudaEventCreateWithFlags(&e1, cudaEventDisableTiming);
    cudaEventCreateWithFlags(&e2, cudaEventDisableTiming);

    // --- main branch: prep (count + x-conv + W-conv) then GEMM1 ---
    k_prep<<<EB, 256>>>(dst, x, (uint4*)h128, W1, W2, W3);
    cudaEventRecord(e1, 0);                           // counts + weights ready

    // --- side branch: CSR build (bsum -> writeptr -> fill4), || with GEMM1 ---
    cudaStreamWaitEvent(s1, e1, 0);
    k_bsum<<<NB_SCAN, 256, 0, s1>>>();
    k_writeptr<<<NB_SCAN, 256, 0, s1>>>();
    k_fill4<<<(NEDGES / 4 + 255) / 256, 256, 0, s1>>>(
        (const int4*)src, (const int4*)dst);
    cudaEventRecord(e2, s1);

    // --- main branch continues: GEMM1 (only needs k_prep) ---
    k_mma<128, 64, true, false, false, false><<<dim3(GB, 1), 256, SM1>>>(
        h128, whi, nullptr, hA);

    // join CSR branch before aggregation
    cudaStreamWaitEvent(0, e2, 0);

    // --- Layer 1 agg ---
    k_agg64<true, true, true, true, false><<<AB, 256>>>(
        (const __half2*)hA, b1, hB);

    // --- Layer 2 ---
    k_agg64<false, false, false, false, false><<<AB, 256>>>(
        (const __half2*)hB, nullptr, hA);
    k_mma<64, 128, false, false, true, true><<<dim3(GB, 2), 256, SM2>>>(
        hA, whi + 8192, b2, h128);

    // --- Layer 3 ---
    k_mma<128, 64, false, true, false, false><<<dim3(GB, 1), 256, SM1>>>(
        h128, whi + 16384, nullptr, hB);
    k_agg64<false, true, false, false, true><<<AB, 256>>>(
        (const __half2*)hB, b3, out);

    cudaEventDestroy(e1);
    cudaEventDestroy(e2);
    cudaStreamDestroy(s1);

    (void)in_sizes; (void)n_in; (void)out_size;
}